// round 1
// baseline (speedup 1.0000x reference)
#include <cuda_runtime.h>

// Problem constants (fixed by setup_inputs)
#define BB   4
#define CC   48
#define HH   99
#define WW   195
#define PSZ  4
#define HS   96     // HH - PSZ + 1
#define WSP  192    // WW - PSZ + 1  (patch positions per row)
#define ND   21     // d = 0..20 (MAX_DISP/stride)
#define NT   64     // threads per CTA
#define NCTA (BB*HS)  // 384

#define INV_TEMP (1.0f/0.07f)

__device__ float g_scratch[NCTA];

__device__ __forceinline__ float dot4(float4 a, float4 b) {
    return a.x*b.x + a.y*b.y + a.z*b.z + a.w*b.w;
}

// Shared memory plan (floats):
//  Phase 1 (channel streaming): 4 buffers of 780 floats each
//    bufT[0]@0, bufS[0]@780, bufT[1]@1560, bufS[1]@2340   (total 3120)
//  Phase 2 (epilogue, reuses same region):
//    A[21*195]@0, Tn[195]@4095, Sn[195]@4290, TP[192]@4485, SP[192]@4677, red[2]@4869
#define SM_FLOATS 4872

// column slot mapping: slot(x) = (x%3)*65 + x/3  (so lanes with consecutive t
// hit consecutive 16B slots -> conflict-free LDS.128)
__device__ __forceinline__ int col_slot(int x) { return (x % 3) * 65 + x / 3; }

__device__ __forceinline__ void fill_channel(float* bT, float* bS,
                                             const float* __restrict__ ft,
                                             const float* __restrict__ fs,
                                             int b, int c, int h, int t) {
    // load rows h..h+3 of channel c into column-major (4 floats per column) slots
    int base_off = ((b * CC + c) * HH + h) * WW;
    for (int x = t; x < WW; x += NT) {
        int s4 = col_slot(x) * 4;
        int off = base_off + x;
        float4 a, v;
        a.x = ft[off];          a.y = ft[off + WW];
        a.z = ft[off + 2*WW];   a.w = ft[off + 3*WW];
        *(float4*)(bT + s4) = a;
        v.x = fs[off];          v.y = fs[off + WW];
        v.z = fs[off + 2*WW];   v.w = fs[off + 3*WW];
        *(float4*)(bS + s4) = v;
    }
}

__global__ void __launch_bounds__(NT)
jino_main_kernel(const float* __restrict__ fs, const float* __restrict__ ft) {
    __shared__ __align__(16) float sm[SM_FLOATS];

    const int t = threadIdx.x;
    const int b = blockIdx.x / HS;
    const int h = blockIdx.x % HS;
    const int base = 3 * t;   // this thread owns columns base, base+1, base+2 (t<64 -> 0..191)
                              // threads t<3 additionally own column 192+t

    float acc0[ND], acc1[ND], acc2[ND], acc3[ND];
    #pragma unroll
    for (int d = 0; d < ND; ++d) { acc0[d]=0.f; acc1[d]=0.f; acc2[d]=0.f; acc3[d]=0.f; }
    float sT0=0.f, sT1=0.f, sT2=0.f, sT3=0.f;
    float sS0=0.f, sS1=0.f, sS2=0.f, sS3=0.f;

    float* bufT[2] = { sm + 0,    sm + 1560 };
    float* bufS[2] = { sm + 780,  sm + 2340 };

    fill_channel(bufT[0], bufS[0], ft, fs, b, 0, h, t);
    __syncthreads();

    #pragma unroll 1
    for (int c = 0; c < CC; ++c) {
        int cur = c & 1;
        if (c + 1 < CC)
            fill_channel(bufT[cur ^ 1], bufS[cur ^ 1], ft, fs, b, c + 1, h, t);

        const float4* bT = (const float4*)bufT[cur];
        const float4* bS = (const float4*)bufS[cur];

        // u columns for this thread: slots t, 65+t, 130+t  (conflict-free)
        float4 u0 = bT[t];
        float4 u1 = bT[65 + t];
        float4 u2 = bT[130 + t];
        sT0 += dot4(u0, u0);
        sT1 += dot4(u1, u1);
        sT2 += dot4(u2, u2);

        // sliding v window: m = base + (mm-20), mm = 0..22
        // slot(m) = r*65 + (t + q - 7) with q=(mm+1)/3, r=(mm+1)%3 (compile-time)
        #pragma unroll
        for (int mm = 0; mm < 23; ++mm) {
            const int q = (mm + 1) / 3;
            const int r = (mm + 1) % 3;
            if (3 * t + mm >= 20) {             // m >= 0
                float4 v = bS[r * 65 + t + (q - 7)];
                if (mm <= 20)            acc0[20 - mm] += dot4(u0, v);
                if (mm >= 1 && mm <= 21) acc1[21 - mm] += dot4(u1, v);
                if (mm >= 2)             acc2[22 - mm] += dot4(u2, v);
                if (mm == 20) sS0 += dot4(v, v);
                if (mm == 21) sS1 += dot4(v, v);
                if (mm == 22) sS2 += dot4(v, v);
            }
        }

        // tail columns 192..194 handled by threads 0..2
        if (t < 3) {
            float4 u3 = bT[t * 65 + 64];        // slot(192+t)
            sT3 += dot4(u3, u3);
            float4 v3 = bS[t * 65 + 64];
            sS3 += dot4(v3, v3);
            #pragma unroll
            for (int d = 0; d < ND; ++d) {
                int m = 192 + t - d;            // >= 172, always valid
                float4 v = bS[(m % 3) * 65 + m / 3];
                acc3[d] += dot4(u3, v);
            }
        }
        __syncthreads();
    }

    // ---- epilogue: window sums, per-row log-softmax CE ----
    float* A  = sm;            // A[d*195 + x]
    float* Tn = sm + 4095;
    float* Sn = sm + 4290;
    float* TP = sm + 4485;
    float* SP = sm + 4677;
    float* red = sm + 4869;

    #pragma unroll
    for (int d = 0; d < ND; ++d) {
        A[d * WW + base]     = acc0[d];
        A[d * WW + base + 1] = acc1[d];
        A[d * WW + base + 2] = acc2[d];
    }
    Tn[base] = sT0; Tn[base + 1] = sT1; Tn[base + 2] = sT2;
    Sn[base] = sS0; Sn[base + 1] = sS1; Sn[base + 2] = sS2;
    if (t < 3) {
        #pragma unroll
        for (int d = 0; d < ND; ++d) A[d * WW + 192 + t] = acc3[d];
        Tn[192 + t] = sT3;
        Sn[192 + t] = sS3;
    }
    __syncthreads();

    for (int i = t; i < WSP; i += NT) {
        TP[i] = Tn[i] + Tn[i+1] + Tn[i+2] + Tn[i+3];
        SP[i] = Sn[i] + Sn[i+1] + Sn[i+2] + Sn[i+3];
    }
    __syncthreads();

    float lsum = 0.f;
    for (int i = t; i < WSP; i += NT) {
        float tn = TP[i];
        float l0 = 0.f;
        float mrun = -1e30f, srun = 0.f;
        #pragma unroll
        for (int d = 0; d < ND; ++d) {
            if (d <= i) {
                const float* Ad = A + d * WW + i;
                float dv = Ad[0] + Ad[1] + Ad[2] + Ad[3];
                float lg = dv * rsqrtf(tn * SP[i - d]) * INV_TEMP;
                if (d == 0) l0 = lg;
                if (lg > mrun) { srun = srun * expf(mrun - lg) + 1.f; mrun = lg; }
                else           { srun += expf(lg - mrun); }
            }
        }
        float lse = mrun + logf(srun);
        lsum += lse - l0;
    }

    // deterministic block reduction (shfl order fixed)
    #pragma unroll
    for (int o = 16; o > 0; o >>= 1)
        lsum += __shfl_down_sync(0xffffffffu, lsum, o);
    int warp = t >> 5;
    if ((t & 31) == 0) red[warp] = lsum;
    __syncthreads();
    if (t == 0) g_scratch[blockIdx.x] = red[0] + red[1];
}

__global__ void jino_reduce_kernel(float* __restrict__ out) {
    __shared__ float s[128];
    int t = threadIdx.x;
    float v = 0.f;
    for (int i = t; i < NCTA; i += 128) v += g_scratch[i];
    s[t] = v;
    __syncthreads();
    #pragma unroll
    for (int st = 64; st > 0; st >>= 1) {
        if (t < st) s[t] += s[t + st];
        __syncthreads();
    }
    if (t == 0) out[0] = s[0] * (1.0f / (float)(BB * HS * WSP));
}

extern "C" void kernel_launch(void* const* d_in, const int* in_sizes, int n_in,
                              void* d_out, int out_size) {
    const float* fs = (const float*)d_in[0];
    const float* ft = (const float*)d_in[1];
    (void)in_sizes; (void)n_in; (void)out_size;
    jino_main_kernel<<<NCTA, NT>>>(fs, ft);
    jino_reduce_kernel<<<1, 128>>>((float*)d_out);
}

// round 2
// speedup vs baseline: 1.3598x; 1.3598x over previous
#include <cuda_runtime.h>

// Problem constants (fixed by setup_inputs)
#define BB   4
#define CC   48
#define HH   99
#define WW   195
#define HS   96     // HH - 4 + 1
#define WSP  192    // WW - 4 + 1
#define ND   21     // d = 0..20
#define NT   256    // threads per CTA (4 groups x 64)
#define NG   4
#define CPG  12     // channels per group
#define NCTA (BB*HS)  // 384

#define INV_TEMP (1.0f/0.07f)

__device__ float g_scratch[NCTA];

__device__ __forceinline__ float dot4(float4 a, float4 b) {
    return a.x*b.x + a.y*b.y + a.z*b.z + a.w*b.w;
}

// SMEM (floats):
//  Phase 1: per-group channel tiles: group g at g*1560: T[780], S[780]  -> 6240
//  Phase 2 (alias over phase 1): A[21*195]@0, Tn[195]@4095, Sn[195]@4290,
//           TP[192]@4485, SP[192]@4677, red[8]@4869
//  tailA (persistent, NOT aliased): @6240, 4 groups * 3 cols * 21 = 252
#define SM_FLOATS (6240 + 252)

__global__ void __launch_bounds__(NT, 2)
jino_main_kernel(const float* __restrict__ fs, const float* __restrict__ ft) {
    __shared__ __align__(16) float sm[SM_FLOATS];

    const int t  = threadIdx.x;
    const int g  = t >> 6;       // channel group 0..3
    const int tl = t & 63;       // thread within group
    const int b  = blockIdx.x / HS;
    const int h  = blockIdx.x % HS;
    const int base = 3 * tl;     // columns base..base+2 owned by this thread
    const int c0 = g * CPG;

    float* bTg = sm + g * 1560;
    float* bSg = bTg + 780;
    float* tailAp = sm + 6240 + g * 63 + tl * ND;  // only meaningful for tl<3

    float acc0[ND], acc1[ND], acc2[ND];
    #pragma unroll
    for (int d = 0; d < ND; ++d) { acc0[d]=0.f; acc1[d]=0.f; acc2[d]=0.f; }
    float sT0=0.f, sT1=0.f, sT2=0.f, sT3=0.f;
    float sS0=0.f, sS1=0.f, sS2=0.f, sS3=0.f;

    // zero the tail accumulator patch
    if (t < NG * 63) sm[6240 + t] = 0.f;

    // register staging for next channel (3 columns per thread: tl, tl+64, tl+128)
    float4 rT[3], rS[3];

    {   // prefetch first channel
        int off0 = ((b * CC + c0) * HH + h) * WW + tl;
        #pragma unroll
        for (int k = 0; k < 3; ++k) {
            int off = off0 + 64 * k;
            rT[k] = make_float4(ft[off], ft[off+WW], ft[off+2*WW], ft[off+3*WW]);
            rS[k] = make_float4(fs[off], fs[off+WW], fs[off+2*WW], fs[off+3*WW]);
        }
    }
    // store first channel to SMEM tiles (slot(x) = (x%3)*65 + x/3 for conflict-free LDS.128)
    #pragma unroll
    for (int k = 0; k < 3; ++k) {
        int x = tl + 64 * k;
        int s4 = ((x % 3) * 65 + x / 3) * 4;
        *(float4*)(bTg + s4) = rT[k];
        *(float4*)(bSg + s4) = rS[k];
    }
    __syncthreads();

    #pragma unroll 1
    for (int cc = 0; cc < CPG; ++cc) {
        const int c = c0 + cc;

        // ---- tail columns 192..194 (threads tl<3), straight from GMEM/SMEM ----
        if (tl < 3) {
            int offu = ((b * CC + c) * HH + h) * WW + 192 + tl;
            float4 u3 = make_float4(ft[offu], ft[offu+WW], ft[offu+2*WW], ft[offu+3*WW]);
            sT3 += dot4(u3, u3);
            float4 v3 = make_float4(fs[offu], fs[offu+WW], fs[offu+2*WW], fs[offu+3*WW]);
            sS3 += dot4(v3, v3);
            int rowbase = offu - (192 + tl);
            #pragma unroll
            for (int d = 0; d < ND; ++d) {
                int m = 192 + tl - d;            // >= 172, always valid
                float4 v;
                if (m >= 192) {
                    int o2 = rowbase + m;
                    v = make_float4(fs[o2], fs[o2+WW], fs[o2+2*WW], fs[o2+3*WW]);
                } else {
                    v = ((const float4*)bSg)[(m % 3) * 65 + m / 3];
                }
                tailAp[d] += dot4(u3, v);
            }
        }

        // ---- prefetch next channel into registers (overlaps with compute) ----
        if (cc + 1 < CPG) {
            int off0 = ((b * CC + (c + 1)) * HH + h) * WW + tl;
            #pragma unroll
            for (int k = 0; k < 3; ++k) {
                int off = off0 + 64 * k;
                rT[k] = make_float4(ft[off], ft[off+WW], ft[off+2*WW], ft[off+3*WW]);
                rS[k] = make_float4(fs[off], fs[off+WW], fs[off+2*WW], fs[off+3*WW]);
            }
        }

        // ---- main banded correlation for this channel ----
        const float4* bT4 = (const float4*)bTg;
        const float4* bS4 = (const float4*)bSg;
        float4 u0 = bT4[tl];
        float4 u1 = bT4[65 + tl];
        float4 u2 = bT4[130 + tl];
        sT0 += dot4(u0, u0);
        sT1 += dot4(u1, u1);
        sT2 += dot4(u2, u2);

        // sliding v window: m = base + (mm-20), mm = 0..22
        #pragma unroll
        for (int mm = 0; mm < 23; ++mm) {
            const int q = (mm + 1) / 3;
            const int r = (mm + 1) % 3;
            if (3 * tl + mm >= 20) {             // m >= 0
                float4 v = bS4[r * 65 + tl + (q - 7)];
                if (mm <= 20)            acc0[20 - mm] += dot4(u0, v);
                if (mm >= 1 && mm <= 21) acc1[21 - mm] += dot4(u1, v);
                if (mm >= 2)             acc2[22 - mm] += dot4(u2, v);
                if (mm == 20) sS0 += dot4(v, v);
                if (mm == 21) sS1 += dot4(v, v);
                if (mm == 22) sS2 += dot4(v, v);
            }
        }
        __syncthreads();                          // all reads of this channel done

        if (cc + 1 < CPG) {
            #pragma unroll
            for (int k = 0; k < 3; ++k) {
                int x = tl + 64 * k;
                int s4 = ((x % 3) * 65 + x / 3) * 4;
                *(float4*)(bTg + s4) = rT[k];
                *(float4*)(bSg + s4) = rS[k];
            }
            __syncthreads();                      // next channel visible
        }
    }

    // ---- epilogue: merge groups (deterministic order), window sums, CE ----
    float* A   = sm;            // A[d*195 + x]
    float* Tn  = sm + 4095;
    float* Sn  = sm + 4290;
    float* TP  = sm + 4485;
    float* SP  = sm + 4677;
    float* red = sm + 4869;
    float* tailA = sm + 6240;

    #pragma unroll 1
    for (int gg = 0; gg < NG; ++gg) {
        if (g == gg) {
            if (gg == 0) {
                #pragma unroll
                for (int d = 0; d < ND; ++d) {
                    A[d * WW + base]     = acc0[d];
                    A[d * WW + base + 1] = acc1[d];
                    A[d * WW + base + 2] = acc2[d];
                }
                Tn[base] = sT0; Tn[base+1] = sT1; Tn[base+2] = sT2;
                Sn[base] = sS0; Sn[base+1] = sS1; Sn[base+2] = sS2;
                if (tl < 3) { Tn[192 + tl] = sT3; Sn[192 + tl] = sS3; }
            } else {
                #pragma unroll
                for (int d = 0; d < ND; ++d) {
                    A[d * WW + base]     += acc0[d];
                    A[d * WW + base + 1] += acc1[d];
                    A[d * WW + base + 2] += acc2[d];
                }
                Tn[base] += sT0; Tn[base+1] += sT1; Tn[base+2] += sT2;
                Sn[base] += sS0; Sn[base+1] += sS1; Sn[base+2] += sS2;
                if (tl < 3) { Tn[192 + tl] += sT3; Sn[192 + tl] += sS3; }
            }
        }
        __syncthreads();
    }

    // tail A columns: sum the 4 group patches
    if (t < 63) {
        int x = t / ND;         // 0..2
        int d = t % ND;
        float v = tailA[0*63 + x*ND + d] + tailA[1*63 + x*ND + d]
                + tailA[2*63 + x*ND + d] + tailA[3*63 + x*ND + d];
        A[d * WW + 192 + x] = v;
    }
    __syncthreads();

    for (int i = t; i < WSP; i += NT) {
        TP[i] = Tn[i] + Tn[i+1] + Tn[i+2] + Tn[i+3];
        SP[i] = Sn[i] + Sn[i+1] + Sn[i+2] + Sn[i+3];
    }
    __syncthreads();

    float lsum = 0.f;
    for (int i = t; i < WSP; i += NT) {
        float tn = TP[i];
        float l0 = 0.f;
        float mrun = -1e30f, srun = 0.f;
        #pragma unroll
        for (int d = 0; d < ND; ++d) {
            if (d <= i) {
                const float* Ad = A + d * WW + i;
                float dv = Ad[0] + Ad[1] + Ad[2] + Ad[3];
                float lg = dv * rsqrtf(tn * SP[i - d]) * INV_TEMP;
                if (d == 0) l0 = lg;
                if (lg > mrun) { srun = srun * expf(mrun - lg) + 1.f; mrun = lg; }
                else           { srun += expf(lg - mrun); }
            }
        }
        float lse = mrun + logf(srun);
        lsum += lse - l0;
    }

    // deterministic block reduction
    #pragma unroll
    for (int o = 16; o > 0; o >>= 1)
        lsum += __shfl_down_sync(0xffffffffu, lsum, o);
    int warp = t >> 5;
    if ((t & 31) == 0) red[warp] = lsum;
    __syncthreads();
    if (t == 0) {
        float s = 0.f;
        #pragma unroll
        for (int w = 0; w < NT/32; ++w) s += red[w];
        g_scratch[blockIdx.x] = s;
    }
}

__global__ void jino_reduce_kernel(float* __restrict__ out) {
    __shared__ float s[128];
    int t = threadIdx.x;
    float v = 0.f;
    for (int i = t; i < NCTA; i += 128) v += g_scratch[i];
    s[t] = v;
    __syncthreads();
    #pragma unroll
    for (int st = 64; st > 0; st >>= 1) {
        if (t < st) s[t] += s[t + st];
        __syncthreads();
    }
    if (t == 0) out[0] = s[0] * (1.0f / (float)(BB * HS * WSP));
}

extern "C" void kernel_launch(void* const* d_in, const int* in_sizes, int n_in,
                              void* d_out, int out_size) {
    const float* fs = (const float*)d_in[0];
    const float* ft = (const float*)d_in[1];
    (void)in_sizes; (void)n_in; (void)out_size;
    jino_main_kernel<<<NCTA, NT>>>(fs, ft);
    jino_reduce_kernel<<<1, 128>>>((float*)d_out);
}

// round 4
// speedup vs baseline: 1.4888x; 1.0949x over previous
#include <cuda_runtime.h>
#include <cstdint>

// Problem constants (fixed by setup_inputs)
#define BB   4
#define CC   48
#define HH   99
#define WW   195
#define HS   96     // HH - 4 + 1
#define WSP  192    // WW - 4 + 1
#define ND   21     // d = 0..20
#define NT   128    // threads per CTA (2 groups x 64)
#define NG   2
#define CPG  24     // channels per group
#define NCTA (BB*HS)  // 384

#define INV_TEMP (1.0f/0.07f)

__device__ float g_scratch[NCTA];
__device__ unsigned int g_count;   // zero at load; reset by last block each launch

__device__ __forceinline__ float dot4(float4 a, float4 b) {
    return a.x*b.x + a.y*b.y + a.z*b.z + a.w*b.w;
}

__device__ __forceinline__ void cp_async4(uint32_t dst, const float* src) {
    asm volatile("cp.async.ca.shared.global [%0], [%1], 4;" :: "r"(dst), "l"(src));
}
#define CP_COMMIT() asm volatile("cp.async.commit_group;" ::: "memory")
#define CP_WAIT0()  asm volatile("cp.async.wait_group 0;" ::: "memory")

// SMEM (floats):
//  Phase 1: group g at g*3120: bufT0[780], bufS0[780], bufT1[780], bufS1[780]
//  Phase 2 (aliases [0,4869)): A[21*195]@0, Tn[195]@4095, Sn[195]@4290,
//           TP[192]@4485, SP[192]@4677
//  tailA (persistent) @6240: NG*63 = 126;  red @ 6368 (4)
#define SM_FLOATS 6376

// column slot: slot(x) = (x%3)*65 + x/3 ; covers x = 0..194
// (x=192,193,194 -> slots 64,129,194)

__global__ void __launch_bounds__(NT, 4)
jino_main_kernel(const float* __restrict__ fs, const float* __restrict__ ft,
                 float* __restrict__ out) {
    __shared__ __align__(16) float sm[SM_FLOATS];
    __shared__ int s_isLast;

    const int t  = threadIdx.x;
    const int g  = t >> 6;       // group 0..1
    const int tl = t & 63;
    const int b  = blockIdx.x / HS;
    const int h  = blockIdx.x % HS;
    const int base = 3 * tl;
    const int c0 = g * CPG;

    float* bufT[2] = { sm + g*3120,        sm + g*3120 + 1560 };
    float* bufS[2] = { sm + g*3120 + 780,  sm + g*3120 + 2340 };
    float* tailAp = sm + 6240 + g * 63 + tl * ND;  // used by tl<3 only
    float* red = sm + 6368;

    // zero tail accumulator patch
    if (t < NG * 63) sm[6240 + t] = 0.f;

    float acc0[ND], acc1[ND], acc2[ND];
    #pragma unroll
    for (int d = 0; d < ND; ++d) { acc0[d]=0.f; acc1[d]=0.f; acc2[d]=0.f; }
    float sT0=0.f, sT1=0.f, sT2=0.f, sT3=0.f;
    float sS0=0.f, sS1=0.f, sS2=0.f, sS3=0.f;

    // ---- async fill of one channel into (bT,bS) ----
    auto fill = [&](int c, float* bT, float* bS) {
        const int off0 = ((b * CC + c) * HH + h) * WW;
        uint32_t bT_u = (uint32_t)__cvta_generic_to_shared(bT);
        uint32_t bS_u = (uint32_t)__cvta_generic_to_shared(bS);
        #pragma unroll
        for (int k = 0; k < 3; ++k) {
            int x = tl + 64 * k;
            uint32_t s16 = (uint32_t)(((x % 3) * 65 + x / 3) * 16);
            const float* pT = ft + off0 + x;
            const float* pS = fs + off0 + x;
            #pragma unroll
            for (int r = 0; r < 4; ++r) {
                cp_async4(bT_u + s16 + 4*r, pT + r * WW);
                cp_async4(bS_u + s16 + 4*r, pS + r * WW);
            }
        }
        if (tl < 3) {
            int x = 192 + tl;
            uint32_t s16 = (uint32_t)((tl * 65 + 64) * 16);
            const float* pT = ft + off0 + x;
            const float* pS = fs + off0 + x;
            #pragma unroll
            for (int r = 0; r < 4; ++r) {
                cp_async4(bT_u + s16 + 4*r, pT + r * WW);
                cp_async4(bS_u + s16 + 4*r, pS + r * WW);
            }
        }
    };

    fill(c0, bufT[0], bufS[0]);
    CP_COMMIT();
    CP_WAIT0();
    __syncthreads();

    #pragma unroll 1
    for (int cc = 0; cc < CPG; ++cc) {
        const int cur = cc & 1;
        if (cc + 1 < CPG) {
            fill(c0 + cc + 1, bufT[cur ^ 1], bufS[cur ^ 1]);
            CP_COMMIT();
        }

        const float4* bT4 = (const float4*)bufT[cur];
        const float4* bS4 = (const float4*)bufS[cur];

        float4 u0 = bT4[tl];
        float4 u1 = bT4[65 + tl];
        float4 u2 = bT4[130 + tl];
        sT0 += dot4(u0, u0);
        sT1 += dot4(u1, u1);
        sT2 += dot4(u2, u2);

        // sliding v window: m = base + (mm-20), mm = 0..22
        #pragma unroll
        for (int mm = 0; mm < 23; ++mm) {
            const int q = (mm + 1) / 3;
            const int r = (mm + 1) % 3;
            if (3 * tl + mm >= 20) {             // m >= 0
                float4 v = bS4[r * 65 + tl + (q - 7)];
                if (mm <= 20)            acc0[20 - mm] += dot4(u0, v);
                if (mm >= 1 && mm <= 21) acc1[21 - mm] += dot4(u1, v);
                if (mm >= 2)             acc2[22 - mm] += dot4(u2, v);
                if (mm == 20) sS0 += dot4(v, v);
                if (mm == 21) sS1 += dot4(v, v);
                if (mm == 22) sS2 += dot4(v, v);
            }
        }

        // tail columns 192..194 (threads tl<3), all from SMEM
        if (tl < 3) {
            float4 u3 = bT4[tl * 65 + 64];       // slot(192+tl)
            sT3 += dot4(u3, u3);
            float4 v3 = bS4[tl * 65 + 64];
            sS3 += dot4(v3, v3);
            #pragma unroll
            for (int d = 0; d < ND; ++d) {
                int m = 192 + tl - d;            // >= 172
                float4 v = bS4[(m % 3) * 65 + m / 3];
                tailAp[d] += dot4(u3, v);
            }
        }

        CP_WAIT0();
        __syncthreads();
    }

    // ---- epilogue: merge groups (deterministic), window sums, CE ----
    float* A   = sm;            // A[d*195 + x]
    float* Tn  = sm + 4095;
    float* Sn  = sm + 4290;
    float* TP  = sm + 4485;
    float* SP  = sm + 4677;
    float* tailA = sm + 6240;

    #pragma unroll 1
    for (int gg = 0; gg < NG; ++gg) {
        if (g == gg) {
            if (gg == 0) {
                #pragma unroll
                for (int d = 0; d < ND; ++d) {
                    A[d * WW + base]     = acc0[d];
                    A[d * WW + base + 1] = acc1[d];
                    A[d * WW + base + 2] = acc2[d];
                }
                Tn[base] = sT0; Tn[base+1] = sT1; Tn[base+2] = sT2;
                Sn[base] = sS0; Sn[base+1] = sS1; Sn[base+2] = sS2;
                if (tl < 3) { Tn[192 + tl] = sT3; Sn[192 + tl] = sS3; }
            } else {
                #pragma unroll
                for (int d = 0; d < ND; ++d) {
                    A[d * WW + base]     += acc0[d];
                    A[d * WW + base + 1] += acc1[d];
                    A[d * WW + base + 2] += acc2[d];
                }
                Tn[base] += sT0; Tn[base+1] += sT1; Tn[base+2] += sT2;
                Sn[base] += sS0; Sn[base+1] += sS1; Sn[base+2] += sS2;
                if (tl < 3) { Tn[192 + tl] += sT3; Sn[192 + tl] += sS3; }
            }
        }
        __syncthreads();
    }

    if (t < 63) {
        int x = t / ND;         // 0..2
        int d = t % ND;
        A[d * WW + 192 + x] = tailA[x * ND + d] + tailA[63 + x * ND + d];
    }
    __syncthreads();

    for (int i = t; i < WSP; i += NT) {
        TP[i] = Tn[i] + Tn[i+1] + Tn[i+2] + Tn[i+3];
        SP[i] = Sn[i] + Sn[i+1] + Sn[i+2] + Sn[i+3];
    }
    __syncthreads();

    float lsum = 0.f;
    for (int i = t; i < WSP; i += NT) {
        float tn = TP[i];
        float l0 = 0.f;
        float mrun = -1e30f, srun = 0.f;
        #pragma unroll
        for (int d = 0; d < ND; ++d) {
            if (d <= i) {
                const float* Ad = A + d * WW + i;
                float dv = Ad[0] + Ad[1] + Ad[2] + Ad[3];
                float lg = dv * rsqrtf(tn * SP[i - d]) * INV_TEMP;
                if (d == 0) l0 = lg;
                if (lg > mrun) { srun = srun * expf(mrun - lg) + 1.f; mrun = lg; }
                else           { srun += expf(lg - mrun); }
            }
        }
        float lse = mrun + logf(srun);
        lsum += lse - l0;
    }

    #pragma unroll
    for (int o = 16; o > 0; o >>= 1)
        lsum += __shfl_down_sync(0xffffffffu, lsum, o);
    int warp = t >> 5;
    if ((t & 31) == 0) red[warp] = lsum;
    __syncthreads();

    if (t == 0) {
        g_scratch[blockIdx.x] = red[0] + red[1] + red[2] + red[3];
        __threadfence();
        unsigned int ticket = atomicAdd(&g_count, 1u);
        s_isLast = (ticket == NCTA - 1) ? 1 : 0;
    }
    __syncthreads();

    if (s_isLast) {
        // deterministic final reduction over 384 partials
        float v = 0.f;
        for (int i = t; i < NCTA; i += NT) v += g_scratch[i];   // 3 iters, fixed order
        #pragma unroll
        for (int o = 16; o > 0; o >>= 1)
            v += __shfl_down_sync(0xffffffffu, v, o);
        if ((t & 31) == 0) red[t >> 5] = v;
        __syncthreads();
        if (t == 0) {
            float s = red[0] + red[1] + red[2] + red[3];
            out[0] = s * (1.0f / (float)(BB * HS * WSP));
            g_count = 0;   // reset for next launch/replay
        }
    }
}

extern "C" void kernel_launch(void* const* d_in, const int* in_sizes, int n_in,
                              void* d_out, int out_size) {
    const float* fs = (const float*)d_in[0];
    const float* ft = (const float*)d_in[1];
    (void)in_sizes; (void)n_in; (void)out_size;
    jino_main_kernel<<<NCTA, NT>>>(fs, ft, (float*)d_out);
}

// round 5
// speedup vs baseline: 2.3869x; 1.6032x over previous
#include <cuda_runtime.h>
#include <cstdint>

// Problem constants (fixed by setup_inputs)
#define BB   4
#define CC   48
#define HH   99
#define WW   195
#define HS   96     // HH - 4 + 1
#define WSP  192    // WW - 4 + 1
#define ND   21     // d = 0..20
#define NT   256    // 2 groups x (3 compute warps + 1 loader warp)
#define CPG  24     // channels per group
#define NCTA (BB*HS)  // 384
#define AW   196    // A row stride

#define INV_TEMP (1.0f/0.07f)

__device__ float g_scratch[NCTA];
__device__ unsigned int g_count;

__device__ __forceinline__ float dot4(float4 a, float4 b) {
    return a.x*b.x + a.y*b.y + a.z*b.z + a.w*b.w;
}

__device__ __forceinline__ void cp_async4(uint32_t dst, const float* src) {
    asm volatile("cp.async.ca.shared.global [%0], [%1], 4;" :: "r"(dst), "l"(src));
}
#define CP_COMMIT() asm volatile("cp.async.commit_group;" ::: "memory")
#define CP_WAIT0()  asm volatile("cp.async.wait_group 0;" ::: "memory")

// SMEM (floats):
//  tiles: group g base g*3136: T0@+0, S0@+784, T1@+1568, S1@+2352  (total 6272)
//  phase-2 alias over [0,4892): A[21*196]@0, Tn[196]@4116, Sn[196]@4312,
//                               TP[192]@4508, SP[192]@4700
//  red[8] @6272 (not aliased)
#define SM_FLOATS 6288

// column slot: slot(x) = (x&1)*98 + (x>>1), x = 0..195 (col 195 never used)

__global__ void __launch_bounds__(NT, 3)
jino_main_kernel(const float* __restrict__ fs, const float* __restrict__ ft,
                 float* __restrict__ out) {
    __shared__ __align__(16) float sm[SM_FLOATS];
    __shared__ int s_isLast;

    const int t    = threadIdx.x;
    const int g    = t >> 7;         // group 0..1
    const int gtid = t & 127;
    const int w    = gtid >> 5;      // warp in group: 0..2 compute, 3 loader
    const int lane = gtid & 31;
    const int b    = blockIdx.x / HS;
    const int h    = blockIdx.x % HS;
    const int c0   = g * CPG;

    float* tile = sm + g * 3136;

    // ---- compute-warp state (w<3): thread owns cols 2*gtid, 2*gtid+1 ----
    float acc0[ND], acc1[ND];
    #pragma unroll
    for (int d = 0; d < ND; ++d) { acc0[d] = 0.f; acc1[d] = 0.f; }
    float sT0 = 0.f, sT1 = 0.f, sS0 = 0.f, sS1 = 0.f;

    // ---- loader-warp state (w==3): tail pairs + norms ----
    const int p0 = lane, p1 = lane + 32;           // (col,d) pairs, p<63 valid
    const int col0 = 192 + p0 / ND, d0 = p0 % ND;
    const int col1 = 192 + p1 / ND, d1 = p1 % ND;
    const int su0 = (col0 & 1) * 98 + (col0 >> 1);
    const int su1 = (col1 & 1) * 98 + (col1 >> 1);
    const int m0 = col0 - d0, m1 = col1 - d1;
    const int sv0 = (m0 & 1) * 98 + (m0 >> 1);
    const int sv1 = (m1 & 1) * 98 + (m1 >> 1);
    float tacc0 = 0.f, tacc1 = 0.f, tsT = 0.f, tsS = 0.f;
    const int ncol = 192 + lane;                   // norm col for lanes 0..2
    const int sn   = (ncol & 1) * 98 + (ncol >> 1);

    // ---- loader fill: coalesced 128B GMEM rows -> column slots ----
    auto fill = [&](int c, int bufsel) {
        float* bT = tile + bufsel * 1568;
        float* bS = bT + 784;
        uint32_t uT = (uint32_t)__cvta_generic_to_shared(bT);
        uint32_t uS = (uint32_t)__cvta_generic_to_shared(bS);
        const int off0 = ((b * CC + c) * HH + h) * WW;
        #pragma unroll
        for (int r = 0; r < 4; ++r) {
            #pragma unroll
            for (int jj = 0; jj < 7; ++jj) {
                int col = lane + 32 * jj;
                if (col < WW) {
                    uint32_t so = (uint32_t)((((col & 1) * 98 + (col >> 1)) * 16) + r * 4);
                    cp_async4(uT + so, ft + off0 + r * WW + col);
                    cp_async4(uS + so, fs + off0 + r * WW + col);
                }
            }
        }
    };

    if (w == 3) { fill(c0, 0); CP_COMMIT(); CP_WAIT0(); }
    __syncthreads();

    #pragma unroll 1
    for (int cc = 0; cc < CPG; ++cc) {
        const int cur = cc & 1;
        const float4* bT4 = (const float4*)(tile + cur * 1568);
        const float4* bS4 = (const float4*)(tile + cur * 1568 + 784);

        if (w < 3) {
            float4 u0 = bT4[gtid];
            float4 u1 = bT4[98 + gtid];
            sT0 += dot4(u0, u0);
            sT1 += dot4(u1, u1);
            // window: k = kk-20, m = 2*gtid + k
            #pragma unroll
            for (int kk = 0; kk < 22; ++kk) {
                const int k = kk - 20;
                const int p = ((k % 2) + 2) % 2;
                const int q = (k - p) / 2;
                if (2 * gtid + k >= 0) {
                    float4 v = bS4[p * 98 + gtid + q];
                    if (k <= 0)   acc0[-k]    += dot4(u0, v);
                    if (k >= -19) acc1[1 - k] += dot4(u1, v);
                    if (k == 0) sS0 += dot4(v, v);
                    if (k == 1) sS1 += dot4(v, v);
                }
            }
        } else {
            if (cc + 1 < CPG) { fill(c0 + cc + 1, cur ^ 1); CP_COMMIT(); }
            // tail columns 192..194
            {
                float4 u = bT4[su0], v = bS4[sv0];
                tacc0 += dot4(u, v);
            }
            if (p1 < 63) {
                float4 u = bT4[su1], v = bS4[sv1];
                tacc1 += dot4(u, v);
            }
            if (lane < 3) {
                float4 un = bT4[sn], vn = bS4[sn];
                tsT += dot4(un, un);
                tsS += dot4(vn, vn);
            }
            if (cc + 1 < CPG) CP_WAIT0();
        }
        __syncthreads();
    }

    // ---- epilogue: merge groups (deterministic order), window sums, CE ----
    float* A   = sm;
    float* Tn  = sm + 4116;
    float* Sn  = sm + 4312;
    float* TP  = sm + 4508;
    float* SP  = sm + 4700;
    float* red = sm + 6272;

    #pragma unroll 1
    for (int gg = 0; gg < 2; ++gg) {
        if (g == gg) {
            if (w < 3) {
                const int x0 = 2 * gtid;
                if (gg == 0) {
                    #pragma unroll
                    for (int d = 0; d < ND; ++d) {
                        A[d * AW + x0]     = acc0[d];
                        A[d * AW + x0 + 1] = acc1[d];
                    }
                    Tn[x0] = sT0; Tn[x0 + 1] = sT1;
                    Sn[x0] = sS0; Sn[x0 + 1] = sS1;
                } else {
                    #pragma unroll
                    for (int d = 0; d < ND; ++d) {
                        A[d * AW + x0]     += acc0[d];
                        A[d * AW + x0 + 1] += acc1[d];
                    }
                    Tn[x0] += sT0; Tn[x0 + 1] += sT1;
                    Sn[x0] += sS0; Sn[x0 + 1] += sS1;
                }
            } else {
                if (gg == 0) {
                    A[d0 * AW + col0] = tacc0;
                    if (p1 < 63) A[d1 * AW + col1] = tacc1;
                    if (lane < 3) { Tn[ncol] = tsT; Sn[ncol] = tsS; }
                } else {
                    A[d0 * AW + col0] += tacc0;
                    if (p1 < 63) A[d1 * AW + col1] += tacc1;
                    if (lane < 3) { Tn[ncol] += tsT; Sn[ncol] += tsS; }
                }
            }
        }
        __syncthreads();
    }

    if (t < WSP) {
        TP[t] = Tn[t] + Tn[t+1] + Tn[t+2] + Tn[t+3];
        SP[t] = Sn[t] + Sn[t+1] + Sn[t+2] + Sn[t+3];
    }
    __syncthreads();

    float lsum = 0.f;
    if (t < WSP) {
        const int i = t;
        float tn = TP[i];
        float l0 = 0.f;
        float mrun = -1e30f, srun = 0.f;
        #pragma unroll
        for (int d = 0; d < ND; ++d) {
            if (d <= i) {
                const float* Ad = A + d * AW + i;
                float dv = Ad[0] + Ad[1] + Ad[2] + Ad[3];
                float lg = dv * rsqrtf(tn * SP[i - d]) * INV_TEMP;
                if (d == 0) l0 = lg;
                if (lg > mrun) { srun = srun * expf(mrun - lg) + 1.f; mrun = lg; }
                else           { srun += expf(lg - mrun); }
            }
        }
        lsum = (mrun + logf(srun)) - l0;
    }

    #pragma unroll
    for (int o = 16; o > 0; o >>= 1)
        lsum += __shfl_down_sync(0xffffffffu, lsum, o);
    if ((t & 31) == 0) red[t >> 5] = lsum;
    __syncthreads();

    if (t == 0) {
        float s = 0.f;
        #pragma unroll
        for (int wv = 0; wv < NT/32; ++wv) s += red[wv];
        g_scratch[blockIdx.x] = s;
        __threadfence();
        unsigned int ticket = atomicAdd(&g_count, 1u);
        s_isLast = (ticket == NCTA - 1) ? 1 : 0;
    }
    __syncthreads();

    if (s_isLast) {
        float v = 0.f;
        for (int i = t; i < NCTA; i += NT) v += g_scratch[i];  // fixed order
        #pragma unroll
        for (int o = 16; o > 0; o >>= 1)
            v += __shfl_down_sync(0xffffffffu, v, o);
        if ((t & 31) == 0) red[t >> 5] = v;
        __syncthreads();
        if (t == 0) {
            float s = 0.f;
            #pragma unroll
            for (int wv = 0; wv < NT/32; ++wv) s += red[wv];
            out[0] = s * (1.0f / (float)(BB * HS * WSP));
            g_count = 0;
        }
    }
}

extern "C" void kernel_launch(void* const* d_in, const int* in_sizes, int n_in,
                              void* d_out, int out_size) {
    const float* fs = (const float*)d_in[0];
    const float* ft = (const float*)d_in[1];
    (void)in_sizes; (void)n_in; (void)out_size;
    jino_main_kernel<<<NCTA, NT>>>(fs, ft, (float*)d_out);
}